// round 2
// baseline (speedup 1.0000x reference)
#include <cuda_runtime.h>

#define H 15

// Weights in constant memory: uniform-address loads become LDCU (uniform-reg
// path, separate port, floor 1/cyc) so the FMA pipe is the only real cost.
__constant__ float cW1[2 * H];
__constant__ float cb1[H];
__constant__ float cW2[H * H];
__constant__ float cb2[H];
__constant__ float cW3[H * H];
__constant__ float cb3[H];
__constant__ float cW4[H];
__constant__ float cb4[1];

__device__ __forceinline__ float fsigmoid(float v) {
    // 1 / (1 + exp(-v)) : 1x MUFU.EX2 + 1x MUFU.RCP (+1 mul each)
    float e = __expf(-v);
    return __fdividef(1.0f, 1.0f + e);
    // v << 0: e -> inf, 1+inf = inf, __fdividef -> 0  (correct limit)
    // v >> 0: e -> 0,  result -> 1                    (correct limit)
}

__global__ __launch_bounds__(256) void mlp_kernel(const float2* __restrict__ x,
                                                  float* __restrict__ out,
                                                  int n) {
    int i = blockIdx.x * blockDim.x + threadIdx.x;
    if (i >= n) return;

    float2 xv = x[i];

    float h1[H];
    float h2[H];

    // Layer 1: Linear(2,H) + SiLU
#pragma unroll
    for (int k = 0; k < H; k++) {
        float a = fmaf(xv.x, cW1[k], fmaf(xv.y, cW1[H + k], cb1[k]));
        h1[k] = a * fsigmoid(a);
    }

    // Layer 2: Linear(H,H) + SiLU
#pragma unroll
    for (int k = 0; k < H; k++) {
        float a = cb2[k];
#pragma unroll
        for (int j = 0; j < H; j++) a = fmaf(h1[j], cW2[j * H + k], a);
        h2[k] = a * fsigmoid(a);
    }

    // Layer 3: Linear(H,H) + SiLU  (reuse h1 as h3 storage)
#pragma unroll
    for (int k = 0; k < H; k++) {
        float a = cb3[k];
#pragma unroll
        for (int j = 0; j < H; j++) a = fmaf(h2[j], cW3[j * H + k], a);
        h1[k] = a * fsigmoid(a);
    }

    // Layer 4: Linear(H,1) + Sigmoid
    float a = cb4[0];
#pragma unroll
    for (int j = 0; j < H; j++) a = fmaf(h1[j], cW4[j], a);

    out[i] = fsigmoid(a);
}

extern "C" void kernel_launch(void* const* d_in, const int* in_sizes, int n_in,
                              void* d_out, int out_size) {
    // Inputs (metadata order): x, W1, b1, W2, b2, W3, b3, W4, b4
    const float* x = (const float*)d_in[0];

    // Graph-capturable D2D memcpy nodes into constant bank.
    cudaMemcpyToSymbolAsync(cW1, d_in[1], 2 * H * sizeof(float), 0,
                            cudaMemcpyDeviceToDevice, 0);
    cudaMemcpyToSymbolAsync(cb1, d_in[2], H * sizeof(float), 0,
                            cudaMemcpyDeviceToDevice, 0);
    cudaMemcpyToSymbolAsync(cW2, d_in[3], H * H * sizeof(float), 0,
                            cudaMemcpyDeviceToDevice, 0);
    cudaMemcpyToSymbolAsync(cb2, d_in[4], H * sizeof(float), 0,
                            cudaMemcpyDeviceToDevice, 0);
    cudaMemcpyToSymbolAsync(cW3, d_in[5], H * H * sizeof(float), 0,
                            cudaMemcpyDeviceToDevice, 0);
    cudaMemcpyToSymbolAsync(cb3, d_in[6], H * sizeof(float), 0,
                            cudaMemcpyDeviceToDevice, 0);
    cudaMemcpyToSymbolAsync(cW4, d_in[7], H * sizeof(float), 0,
                            cudaMemcpyDeviceToDevice, 0);
    cudaMemcpyToSymbolAsync(cb4, d_in[8], 1 * sizeof(float), 0,
                            cudaMemcpyDeviceToDevice, 0);

    int n = in_sizes[0] / 2;  // rows: x is [N, 2]
    int threads = 256;
    int blocks = (n + threads - 1) / threads;
    mlp_kernel<<<blocks, threads>>>((const float2*)x, (float*)d_out, n);
}

// round 5
// speedup vs baseline: 1.4803x; 1.4803x over previous
#include <cuda_runtime.h>

#define H 15
#define NPACK 541
// packed-weight layout (u64 {w,w} per weight)
#define OW1 0      // 30
#define OB1 30     // 15
#define OW2 45     // 225
#define OB2 270    // 15
#define OW3 285    // 225
#define OB3 510    // 15
#define OW4 525    // 15
#define OB4 540    // 1

typedef unsigned long long u64;

__device__ u64 g_packed[NPACK];
__constant__ u64 cw[NPACK];

// ---- packed f32x2 helpers (sm_100+ PTX) ----
__device__ __forceinline__ u64 pk(float a, float b) {
    u64 r; asm("mov.b64 %0,{%1,%2};" : "=l"(r) : "f"(a), "f"(b)); return r;
}
__device__ __forceinline__ void upk(u64 v, float& a, float& b) {
    asm("mov.b64 {%0,%1},%2;" : "=f"(a), "=f"(b) : "l"(v));
}
__device__ __forceinline__ u64 fma2(u64 a, u64 b, u64 c) {
    u64 r; asm("fma.rn.f32x2 %0,%1,%2,%3;" : "=l"(r) : "l"(a), "l"(b), "l"(c)); return r;
}
__device__ __forceinline__ u64 mul2(u64 a, u64 b) {
    u64 r; asm("mul.rn.f32x2 %0,%1,%2;" : "=l"(r) : "l"(a), "l"(b)); return r;
}
__device__ __forceinline__ u64 add2(u64 a, u64 b) {
    u64 r; asm("add.rn.f32x2 %0,%1,%2;" : "=l"(r) : "l"(a), "l"(b)); return r;
}

// sigmoid on both lanes: 1/(1+exp(-v)) via ex2.approx + rcp.approx.
// v<<0: ex2->inf, rcp(inf)=0 ; v>>0: ex2->0, rcp(1)=1  (correct limits)
__device__ __forceinline__ u64 sigmoid2(u64 a, u64 nlog2e, u64 one2) {
    u64 t = mul2(a, nlog2e);           // -v * log2(e), packed
    float t0, t1; upk(t, t0, t1);
    float e0, e1;
    asm("ex2.approx.f32 %0,%1;" : "=f"(e0) : "f"(t0));
    asm("ex2.approx.f32 %0,%1;" : "=f"(e1) : "f"(t1));
    u64 d = add2(pk(e0, e1), one2);    // 1 + exp(-v), packed
    float d0, d1; upk(d, d0, d1);
    float r0, r1;
    asm("rcp.approx.f32 %0,%1;" : "=f"(r0) : "f"(d0));
    asm("rcp.approx.f32 %0,%1;" : "=f"(r1) : "f"(d1));
    return pk(r0, r1);
}

// Duplicate each scalar weight into a {w,w} u64 pair.
__global__ void prep_kernel(const float* __restrict__ W1, const float* __restrict__ b1,
                            const float* __restrict__ W2, const float* __restrict__ b2,
                            const float* __restrict__ W3, const float* __restrict__ b3,
                            const float* __restrict__ W4, const float* __restrict__ b4) {
    int i = threadIdx.x;
    float v;
    if      (i < OB1) v = W1[i - OW1];
    else if (i < OW2) v = b1[i - OB1];
    else if (i < OB2) v = W2[i - OW2];
    else if (i < OW3) v = b2[i - OB2];
    else if (i < OB3) v = W3[i - OW3];
    else if (i < OW4) v = b3[i - OB3];
    else if (i < OB4) v = W4[i - OW4];
    else if (i == OB4) v = b4[0];
    else return;
    u64 p; asm("mov.b64 %0,{%1,%1};" : "=l"(p) : "f"(v));
    g_packed[i] = p;
}

// 2 rows per thread, all math packed f32x2.
__global__ __launch_bounds__(256) void mlp2_kernel(const float4* __restrict__ x,
                                                   float2* __restrict__ out,
                                                   int npair) {
    int i = blockIdx.x * blockDim.x + threadIdx.x;
    if (i >= npair) return;

    const u64 nlog2e = pk(-1.4426950408889634f, -1.4426950408889634f);
    const u64 one2   = pk(1.0f, 1.0f);

    float4 xv = x[i];                  // {x0,y0,x1,y1} = rows 2i, 2i+1
    u64 xx = pk(xv.x, xv.z);
    u64 yy = pk(xv.y, xv.w);

    u64 h1[H], h2[H];

    // Layer 1: Linear(2,H) + SiLU
#pragma unroll
    for (int k = 0; k < H; k++) {
        u64 a = fma2(xx, cw[OW1 + k], fma2(yy, cw[OW1 + H + k], cw[OB1 + k]));
        h1[k] = mul2(a, sigmoid2(a, nlog2e, one2));
    }

    // Layer 2: Linear(H,H) + SiLU
#pragma unroll
    for (int k = 0; k < H; k++) {
        u64 a = cw[OB2 + k];
#pragma unroll
        for (int j = 0; j < H; j++) a = fma2(h1[j], cw[OW2 + j * H + k], a);
        h2[k] = mul2(a, sigmoid2(a, nlog2e, one2));
    }

    // Layer 3: Linear(H,H) + SiLU (reuse h1)
#pragma unroll
    for (int k = 0; k < H; k++) {
        u64 a = cw[OB3 + k];
#pragma unroll
        for (int j = 0; j < H; j++) a = fma2(h2[j], cw[OW3 + j * H + k], a);
        h1[k] = mul2(a, sigmoid2(a, nlog2e, one2));
    }

    // Layer 4: Linear(H,1) + Sigmoid
    u64 a = cw[OB4];
#pragma unroll
    for (int j = 0; j < H; j++) a = fma2(h1[j], cw[OW4 + j], a);
    u64 s = sigmoid2(a, nlog2e, one2);

    float s0, s1; upk(s, s0, s1);
    out[i] = make_float2(s0, s1);
}

extern "C" void kernel_launch(void* const* d_in, const int* in_sizes, int n_in,
                              void* d_out, int out_size) {
    // Inputs: x, W1, b1, W2, b2, W3, b3, W4, b4
    const float* x = (const float*)d_in[0];

    prep_kernel<<<1, 544>>>((const float*)d_in[1], (const float*)d_in[2],
                            (const float*)d_in[3], (const float*)d_in[4],
                            (const float*)d_in[5], (const float*)d_in[6],
                            (const float*)d_in[7], (const float*)d_in[8]);

    void* src = nullptr;
    cudaGetSymbolAddress(&src, g_packed);  // host-side query, capture-safe
    cudaMemcpyToSymbolAsync(cw, src, NPACK * sizeof(u64), 0,
                            cudaMemcpyDeviceToDevice, 0);

    int n = in_sizes[0] / 2;   // rows
    int npair = n / 2;         // 2 rows per thread
    int threads = 256;
    int blocks = (npair + threads - 1) / threads;
    mlp2_kernel<<<blocks, threads>>>((const float4*)x, (float2*)d_out, npair);
}